// round 5
// baseline (speedup 1.0000x reference)
#include <cuda_runtime.h>
#include <cstdint>

#define TOK_N 131072   // B*T = 64*2048
#define DD    256      // D = V = 256
#define TT    2048

typedef unsigned long long ull;

// Scratch (device globals: allocation-free rule)
__device__ float g_wx  [TOK_N * DD];   // 128 MB
__device__ float g_gate[TOK_N * DD];   // 128 MB
__device__ float g_ys  [TOK_N * DD];   // 128 MB

// packed f32x2 FMA / ADD (Blackwell-only; ptxas never auto-fuses these)
#define FMA2(d, a, b, c) \
    asm("fma.rn.f32x2 %0, %1, %2, %3;" : "=l"(d) : "l"(a), "l"(b), "l"(c))
#define ADD2(d, a, b) \
    asm("add.rn.f32x2 %0, %1, %2;" : "=l"(d) : "l"(a), "l"(b))
#define PACK2(d, x) \
    asm("mov.b64 %0, {%1, %1};" : "=l"(d) : "f"(x))
#define UNPACK2(lo, hi, v) \
    asm("mov.b64 {%0, %1}, %2;" : "=f"(lo), "=f"(hi) : "l"(v))

__device__ __forceinline__ uint32_t smem_u32(const void* p) {
    uint32_t a;
    asm("{ .reg .u64 t; cvta.to.shared.u64 t, %1; cvt.u32.u64 %0, t; }"
        : "=r"(a) : "l"(p));
    return a;
}

// ---------------------------------------------------------------------------
// Kernel 1: fused embed-gather + dual projection, 128x128 tile, f32x2.
//   g_wx[m][e]   = sum_d E[tok[m]][d] * Wx[e][d]
//   g_gate[m][e] = sigmoid( sum_d E[tok[m]][d] * Wz[e][d] )
// ---------------------------------------------------------------------------
constexpr int GBM = 128, GBN = 128, GBK = 16, GPAD = 4;

__global__ __launch_bounds__(256, 1) void proj_kernel(
    const int*   __restrict__ tokens,
    const float* __restrict__ E,
    const float* __restrict__ Wx,
    const float* __restrict__ Wz)
{
    __shared__ float As[GBK][GBM + GPAD];
    __shared__ float Bxs[GBK][GBN + GPAD];
    __shared__ float Bzs[GBK][GBN + GPAD];

    const int tid  = threadIdx.x;
    const int m0   = blockIdx.x * GBM;
    const int n0   = blockIdx.y * GBN;

    // loader mapping: row = tid>>1 (0..127), 8 consecutive floats at (tid&1)*8
    const int lrow = tid >> 1;
    const int lk8  = (tid & 1) * 8;
    const int tokr = tokens[m0 + lrow];

    // compute mapping: 8 warps in 4x2, lane 4x8; 8x8 frag
    const int warp = tid >> 5, lane = tid & 31;
    const int rb = (warp >> 1) * 32 + (lane >> 3) * 8;
    const int cb = (warp & 1) * 64 + (lane & 7) * 8;

    ull accx[8][4], accz[8][4];
#pragma unroll
    for (int i = 0; i < 8; i++)
#pragma unroll
        for (int j = 0; j < 4; j++) { accx[i][j] = 0ull; accz[i][j] = 0ull; }

    for (int k0 = 0; k0 < DD; k0 += GBK) {
        float4 va0 = *(const float4*)&E [(size_t)tokr * DD + k0 + lk8];
        float4 va1 = *(const float4*)&E [(size_t)tokr * DD + k0 + lk8 + 4];
        float4 vx0 = *(const float4*)&Wx[(size_t)(n0 + lrow) * DD + k0 + lk8];
        float4 vx1 = *(const float4*)&Wx[(size_t)(n0 + lrow) * DD + k0 + lk8 + 4];
        float4 vz0 = *(const float4*)&Wz[(size_t)(n0 + lrow) * DD + k0 + lk8];
        float4 vz1 = *(const float4*)&Wz[(size_t)(n0 + lrow) * DD + k0 + lk8 + 4];

        __syncthreads();   // previous tile's readers done

        As[lk8+0][lrow] = va0.x; As[lk8+1][lrow] = va0.y;
        As[lk8+2][lrow] = va0.z; As[lk8+3][lrow] = va0.w;
        As[lk8+4][lrow] = va1.x; As[lk8+5][lrow] = va1.y;
        As[lk8+6][lrow] = va1.z; As[lk8+7][lrow] = va1.w;

        Bxs[lk8+0][lrow] = vx0.x; Bxs[lk8+1][lrow] = vx0.y;
        Bxs[lk8+2][lrow] = vx0.z; Bxs[lk8+3][lrow] = vx0.w;
        Bxs[lk8+4][lrow] = vx1.x; Bxs[lk8+5][lrow] = vx1.y;
        Bxs[lk8+6][lrow] = vx1.z; Bxs[lk8+7][lrow] = vx1.w;

        Bzs[lk8+0][lrow] = vz0.x; Bzs[lk8+1][lrow] = vz0.y;
        Bzs[lk8+2][lrow] = vz0.z; Bzs[lk8+3][lrow] = vz0.w;
        Bzs[lk8+4][lrow] = vz1.x; Bzs[lk8+5][lrow] = vz1.y;
        Bzs[lk8+6][lrow] = vz1.z; Bzs[lk8+7][lrow] = vz1.w;

        __syncthreads();

#pragma unroll
        for (int kk = 0; kk < GBK; kk++) {
            float4 a0 = *(const float4*)&As[kk][rb];
            float4 a1 = *(const float4*)&As[kk][rb + 4];
            ulonglong2 bx01 = *(const ulonglong2*)&Bxs[kk][cb];
            ulonglong2 bx23 = *(const ulonglong2*)&Bxs[kk][cb + 4];
            ulonglong2 bz01 = *(const ulonglong2*)&Bzs[kk][cb];
            ulonglong2 bz23 = *(const ulonglong2*)&Bzs[kk][cb + 4];
            const float av[8] = {a0.x, a0.y, a0.z, a0.w, a1.x, a1.y, a1.z, a1.w};
#pragma unroll
            for (int i = 0; i < 8; i++) {
                ull aa; PACK2(aa, av[i]);
                FMA2(accx[i][0], aa, bx01.x, accx[i][0]);
                FMA2(accx[i][1], aa, bx01.y, accx[i][1]);
                FMA2(accx[i][2], aa, bx23.x, accx[i][2]);
                FMA2(accx[i][3], aa, bx23.y, accx[i][3]);
                FMA2(accz[i][0], aa, bz01.x, accz[i][0]);
                FMA2(accz[i][1], aa, bz01.y, accz[i][1]);
                FMA2(accz[i][2], aa, bz23.x, accz[i][2]);
                FMA2(accz[i][3], aa, bz23.y, accz[i][3]);
            }
        }
    }

#pragma unroll
    for (int i = 0; i < 8; i++) {
        float x[8], z[8];
        UNPACK2(x[0], x[1], accx[i][0]); UNPACK2(x[2], x[3], accx[i][1]);
        UNPACK2(x[4], x[5], accx[i][2]); UNPACK2(x[6], x[7], accx[i][3]);
        UNPACK2(z[0], z[1], accz[i][0]); UNPACK2(z[2], z[3], accz[i][1]);
        UNPACK2(z[4], z[5], accz[i][2]); UNPACK2(z[6], z[7], accz[i][3]);
        float* wrow = &g_wx  [(size_t)(m0 + rb + i) * DD + n0 + cb];
        float* grow = &g_gate[(size_t)(m0 + rb + i) * DD + n0 + cb];
        *(float4*)&wrow[0] = make_float4(x[0], x[1], x[2], x[3]);
        *(float4*)&wrow[4] = make_float4(x[4], x[5], x[6], x[7]);
        float4 s0, s1;
        s0.x = 1.f/(1.f+__expf(-z[0])); s0.y = 1.f/(1.f+__expf(-z[1]));
        s0.z = 1.f/(1.f+__expf(-z[2])); s0.w = 1.f/(1.f+__expf(-z[3]));
        s1.x = 1.f/(1.f+__expf(-z[4])); s1.y = 1.f/(1.f+__expf(-z[5]));
        s1.z = 1.f/(1.f+__expf(-z[6])); s1.w = 1.f/(1.f+__expf(-z[7]));
        *(float4*)&grow[0] = s0;
        *(float4*)&grow[4] = s1;
    }
}

// ---------------------------------------------------------------------------
// Kernel 2: Elman recurrence v3.
//  - warp-self-contained: thread = 1 output x 128-k half (lane&1), one
//    shfl_xor(1) reduction; no __syncthreads anywhere in the loop.
//  - f32x2 weights in registers (64 ull/thread), 4 accumulator chains.
//  - mbarrier with 16 arrivals/step (elected lane per warp, local+remote).
//  - triple-buffered h (tolerates the 1-phase arrival borrow).
// ---------------------------------------------------------------------------
__global__ void __cluster_dims__(2, 1, 1) __launch_bounds__(256, 1)
rnn_kernel(const float* __restrict__ Wh)
{
    __shared__ __align__(16) float h_s[3][DD];
    __shared__ __align__(8) ull mbar;

    const int tid  = threadIdx.x;
    const int warp = tid >> 5;
    const int lane = tid & 31;
    const int kh   = lane & 1;              // k half
    const int b    = blockIdx.x >> 1;
    const int half = blockIdx.x & 1;        // cluster rank
    const int eL   = warp * 16 + (lane >> 1);
    const int eg   = half * 128 + eL;       // my output row
    const int k0   = kh * 128;

    // 128 weights as 64 packed f32x2
    ull wp[64];
    {
        const ull* wrow = (const ull*)(Wh + (size_t)eg * DD + k0);
#pragma unroll
        for (int j = 0; j < 64; j++) wp[j] = wrow[j];
    }

    h_s[0][tid] = 0.f;

    const uint32_t mbar_a = smem_u32(&mbar);
    const uint32_t h_a    = smem_u32(&h_s[0][0]);
    uint32_t mbar_peer, h_peer;
    asm("mapa.shared::cluster.u32 %0, %1, %2;" : "=r"(mbar_peer) : "r"(mbar_a), "r"(half ^ 1));
    asm("mapa.shared::cluster.u32 %0, %1, %2;" : "=r"(h_peer)    : "r"(h_a),    "r"(half ^ 1));

    if (tid == 0)
        asm volatile("mbarrier.init.shared.b64 [%0], %1;" :: "r"(mbar_a), "r"(16) : "memory");

    asm volatile("barrier.cluster.arrive.aligned;" ::: "memory");
    asm volatile("barrier.cluster.wait.aligned;"   ::: "memory");

    const float* wx_p = g_wx   + (size_t)b * TT * DD;
    const float* gt_p = g_gate + (size_t)b * TT * DD;
    float*       y_p  = g_ys   + (size_t)b * TT * DD;

    const bool writer = (kh == 0);
    float wx_c = 0.f, gt_c = 0.f, wx_n = 0.f, gt_n = 0.f;
    if (writer) { wx_c = wx_p[eg]; gt_c = gt_p[eg]; }

    int rbuf = 0;
    for (int t = 0; t < TT; t++) {
        int wbuf = rbuf + 1; if (wbuf == 3) wbuf = 0;

        if (writer && t + 1 < TT) {
            wx_n = wx_p[(size_t)(t + 1) * DD + eg];
            gt_n = gt_p[(size_t)(t + 1) * DD + eg];
        }

        // my 128-k half: 32 x 16B loads (2 distinct addrs/instr -> broadcast)
        const ulonglong2* hp = (const ulonglong2*)&h_s[rbuf][k0];
        ull acc0 = 0, acc1 = 0, acc2 = 0, acc3 = 0;
#pragma unroll
        for (int i = 0; i < 32; i += 4) {
            ulonglong2 h0 = hp[i], h1 = hp[i+1], h2 = hp[i+2], h3 = hp[i+3];
            FMA2(acc0, wp[2*i+0], h0.x, acc0);
            FMA2(acc1, wp[2*i+1], h0.y, acc1);
            FMA2(acc2, wp[2*i+2], h1.x, acc2);
            FMA2(acc3, wp[2*i+3], h1.y, acc3);
            FMA2(acc0, wp[2*i+4], h2.x, acc0);
            FMA2(acc1, wp[2*i+5], h2.y, acc1);
            FMA2(acc2, wp[2*i+6], h3.x, acc2);
            FMA2(acc3, wp[2*i+7], h3.y, acc3);
        }
        ADD2(acc0, acc0, acc1);
        ADD2(acc2, acc2, acc3);
        ADD2(acc0, acc0, acc2);
        float lo, hi;
        UNPACK2(lo, hi, acc0);
        float sum = lo + hi;
        sum += __shfl_xor_sync(0xffffffffu, sum, 1);   // combine two k-halves

        if (writer) {
            const float hn = tanhf(wx_c + sum);
            y_p[(size_t)t * DD + eg] = hn * gt_c;
            h_s[wbuf][eg] = hn;
            asm volatile("st.shared::cluster.f32 [%0], %1;"
                         :: "r"(h_peer + (uint32_t)(wbuf * DD + eg) * 4u), "f"(hn) : "memory");
            wx_c = wx_n; gt_c = gt_n;
        }
        __syncwarp();
        if (lane == 0) {
            asm volatile("mbarrier.arrive.release.cluster.shared::cta.b64 _, [%0];"
                         :: "r"(mbar_a) : "memory");
            asm volatile("mbarrier.arrive.release.cluster.shared::cluster.b64 _, [%0];"
                         :: "r"(mbar_peer) : "memory");
        }

        const uint32_t par = (uint32_t)(t & 1);
        uint32_t done;
        do {
            asm volatile(
                "{\n\t.reg .pred p;\n\t"
                "mbarrier.try_wait.parity.acquire.cluster.shared::cta.b64 p, [%1], %2, 0x989680;\n\t"
                "selp.b32 %0, 1, 0, p;\n\t}"
                : "=r"(done) : "r"(mbar_a), "r"(par) : "memory");
        } while (!done);

        rbuf = wbuf;
    }

    asm volatile("barrier.cluster.arrive.aligned;" ::: "memory");
    asm volatile("barrier.cluster.wait.aligned;"   ::: "memory");
}

// ---------------------------------------------------------------------------
// Kernel 3: tied head, 128x128 tile, f32x2.  out[m][v] = sum_d ys[m][d]*E[v][d]
// ---------------------------------------------------------------------------
__global__ __launch_bounds__(256, 1) void head_kernel(
    const float* __restrict__ E, float* __restrict__ out)
{
    __shared__ float As[GBK][GBM + GPAD];
    __shared__ float Bs[GBK][GBN + GPAD];

    const int tid  = threadIdx.x;
    const int m0   = blockIdx.x * GBM;
    const int n0   = blockIdx.y * GBN;

    const int lrow = tid >> 1;
    const int lk8  = (tid & 1) * 8;

    const int warp = tid >> 5, lane = tid & 31;
    const int rb = (warp >> 1) * 32 + (lane >> 3) * 8;
    const int cb = (warp & 1) * 64 + (lane & 7) * 8;

    ull acc[8][4];
#pragma unroll
    for (int i = 0; i < 8; i++)
#pragma unroll
        for (int j = 0; j < 4; j++) acc[i][j] = 0ull;

    for (int k0 = 0; k0 < DD; k0 += GBK) {
        float4 va0 = *(const float4*)&g_ys[(size_t)(m0 + lrow) * DD + k0 + lk8];
        float4 va1 = *(const float4*)&g_ys[(size_t)(m0 + lrow) * DD + k0 + lk8 + 4];
        float4 vb0 = *(const float4*)&E  [(size_t)(n0 + lrow) * DD + k0 + lk8];
        float4 vb1 = *(const float4*)&E  [(size_t)(n0 + lrow) * DD + k0 + lk8 + 4];

        __syncthreads();

        As[lk8+0][lrow] = va0.x; As[lk8+1][lrow] = va0.y;
        As[lk8+2][lrow] = va0.z; As[lk8+3][lrow] = va0.w;
        As[lk8+4][lrow] = va1.x; As[lk8+5][lrow] = va1.y;
        As[lk8+6][lrow] = va1.z; As[lk8+7][lrow] = va1.w;

        Bs[lk8+0][lrow] = vb0.x; Bs[lk8+1][lrow] = vb0.y;
        Bs[lk8+2][lrow] = vb0.z; Bs[lk8+3][lrow] = vb0.w;
        Bs[lk8+4][lrow] = vb1.x; Bs[lk8+5][lrow] = vb1.y;
        Bs[lk8+6][lrow] = vb1.z; Bs[lk8+7][lrow] = vb1.w;

        __syncthreads();

#pragma unroll
        for (int kk = 0; kk < GBK; kk++) {
            float4 a0 = *(const float4*)&As[kk][rb];
            float4 a1 = *(const float4*)&As[kk][rb + 4];
            ulonglong2 b01 = *(const ulonglong2*)&Bs[kk][cb];
            ulonglong2 b23 = *(const ulonglong2*)&Bs[kk][cb + 4];
            const float av[8] = {a0.x, a0.y, a0.z, a0.w, a1.x, a1.y, a1.z, a1.w};
#pragma unroll
            for (int i = 0; i < 8; i++) {
                ull aa; PACK2(aa, av[i]);
                FMA2(acc[i][0], aa, b01.x, acc[i][0]);
                FMA2(acc[i][1], aa, b01.y, acc[i][1]);
                FMA2(acc[i][2], aa, b23.x, acc[i][2]);
                FMA2(acc[i][3], aa, b23.y, acc[i][3]);
            }
        }
    }

#pragma unroll
    for (int i = 0; i < 8; i++) {
        float x[8];
        UNPACK2(x[0], x[1], acc[i][0]); UNPACK2(x[2], x[3], acc[i][1]);
        UNPACK2(x[4], x[5], acc[i][2]); UNPACK2(x[6], x[7], acc[i][3]);
        float* orow = &out[(size_t)(m0 + rb + i) * DD + n0 + cb];
        *(float4*)&orow[0] = make_float4(x[0], x[1], x[2], x[3]);
        *(float4*)&orow[4] = make_float4(x[4], x[5], x[6], x[7]);
    }
}

// ---------------------------------------------------------------------------
extern "C" void kernel_launch(void* const* d_in, const int* in_sizes, int n_in,
                              void* d_out, int out_size)
{
    const int*   tokens = (const int*)  d_in[0];
    const float* E      = (const float*)d_in[1];
    const float* Wx     = (const float*)d_in[2];
    const float* Wh     = (const float*)d_in[3];
    const float* Wz     = (const float*)d_in[4];
    float* out = (float*)d_out;

    dim3 gg(TOK_N / GBM, DD / GBN);
    proj_kernel<<<gg, 256>>>(tokens, E, Wx, Wz);
    rnn_kernel<<<128, 256>>>(Wh);
    head_kernel<<<gg, 256>>>(E, out);
}